// round 15
// baseline (speedup 1.0000x reference)
#include <cuda_runtime.h>
#include <math.h>

#define BB 4
#define SS 512
#define JJ 24
#define HH 128
#define NHEAD 8
#define HSZ 16
#define WS 132   // padded smem stride for GEMM kernels

// Scratch (device globals — no allocation allowed)
// q/k/v layout: (b, j, s, col) with col = n*16 + d
// NOTE: g_q holds Q pre-scaled by 1/sqrt(16) (folded into W_q at load).
__device__ float g_q[BB*JJ*SS*HH];
__device__ float g_k[BB*JJ*SS*HH];
__device__ float g_v[BB*JJ*SS*HH];
__device__ float g_ao[BB*SS*JJ*HH];   // attention out, (b,s,j,h) h=n*16+d

// ---- tf32 helpers ----------------------------------------------------------
__device__ __forceinline__ unsigned f2tf32(float f) {
    unsigned r; asm("cvt.rna.tf32.f32 %0, %1;" : "=r"(r) : "f"(f)); return r;
}
// tf32 mma: activation operands are raw fp32 bits (HW truncates); weights rounded.
__device__ __forceinline__ void mma8(float* c, unsigned a0, unsigned a1,
                                     unsigned a2, unsigned a3,
                                     unsigned b0, unsigned b1) {
    asm("mma.sync.aligned.m16n8k8.row.col.f32.tf32.tf32.f32 "
        "{%0,%1,%2,%3},{%4,%5,%6,%7},{%8,%9},{%0,%1,%2,%3};"
        : "+f"(c[0]), "+f"(c[1]), "+f"(c[2]), "+f"(c[3])
        : "r"(a0), "r"(a1), "r"(a2), "r"(a3), "r"(b0), "r"(b1));
}

// ---------------------------------------------------------------------------
// Kernel 1: QKV projection via tf32 mma. Row-split: 256 rows per block.
// grid (24, 8, 3): y = b*2 + rowHalf. Weights rounded (rna), X raw bits.
// block 256, smem = (128+64)*132*4 = 101376 B
// ---------------------------------------------------------------------------
__global__ void __launch_bounds__(256) qkv_kernel(const float* __restrict__ x,
                           const float* __restrict__ qm,
                           const float* __restrict__ km,
                           const float* __restrict__ vm) {
    const int j  = blockIdx.x;
    const int b  = blockIdx.y >> 1;
    const int s0base = (blockIdx.y & 1) * 256;   // row half
    const int m  = blockIdx.z;
    const float* W = (m == 0) ? qm : ((m == 1) ? km : vm);
    float* dst = (m == 0) ? g_q : ((m == 1) ? g_k : g_v);
    const float wscale = (m == 0) ? 0.25f : 1.0f;   // fold 1/sqrt(HS) into W_q

    extern __shared__ unsigned smu[];
    unsigned* sW = smu;             // [col][h] transposed, stride WS
    unsigned* sX = smu + HH * WS;   // [64 rows][h], stride WS

    const int tid  = threadIdx.x;
    const int warp = tid >> 5, lane = tid & 31;
    const int gid  = lane >> 2, tig = lane & 3;
    const int wr0  = (warp & 1) * 32;
    const int wc0  = (warp >> 1) * 32;

    // one-time weight load: rounded tf32 (error mitigation, outside hot loop)
    for (int i4 = tid; i4 < (HH * HH) / 4; i4 += 256) {
        const int idx = i4 * 4;
        const int n8 = idx >> 11, rem = idx & 2047;
        const int h = rem >> 4, d = rem & 15;
        const float4 w = *(const float4*)&W[(size_t)(n8 * JJ + j) * 2048 + rem];
        const int col = n8 * HSZ + d;
        sW[(col + 0) * WS + h] = f2tf32(w.x * wscale);
        sW[(col + 1) * WS + h] = f2tf32(w.y * wscale);
        sW[(col + 2) * WS + h] = f2tf32(w.z * wscale);
        sW[(col + 3) * WS + h] = f2tf32(w.w * wscale);
    }

    float* db_all = dst + (size_t)((b * JJ + j) * SS + s0base) * HH;

    float4 xr[8];
    #pragma unroll
    for (int q = 0; q < 8; q++) {
        const int i4 = tid + q * 256;
        const int r = i4 >> 5, h = (i4 & 31) * 4;
        xr[q] = *(const float4*)&x[((size_t)(b * SS + s0base + r) * JJ + j) * HH + h];
    }

    for (int c0 = 0; c0 < 256; c0 += 64) {
        __syncthreads();
        #pragma unroll
        for (int q = 0; q < 8; q++) {
            const int i4 = tid + q * 256;
            const int r = i4 >> 5, h = (i4 & 31) * 4;
            *(float4*)&sX[r * WS + h] = xr[q];   // raw bits, no cvt
        }
        if (c0 + 64 < 256) {
            #pragma unroll
            for (int q = 0; q < 8; q++) {
                const int i4 = tid + q * 256;
                const int r = i4 >> 5, h = (i4 & 31) * 4;
                xr[q] = *(const float4*)&x[((size_t)(b * SS + s0base + c0 + 64 + r) * JJ + j) * HH + h];
            }
        }
        __syncthreads();

        float ccA[4][4], ccB[4][4];
        #pragma unroll
        for (int cf = 0; cf < 4; cf++)
            #pragma unroll
            for (int i = 0; i < 4; i++) { ccA[cf][i] = 0.f; ccB[cf][i] = 0.f; }

        #pragma unroll
        for (int k0 = 0; k0 < HH; k0 += 8) {
            const int rA = (wr0 + gid) * WS + k0 + tig;
            const unsigned aA0 = sX[rA];
            const unsigned aA1 = sX[rA + 8 * WS];
            const unsigned aA2 = sX[rA + 4];
            const unsigned aA3 = sX[rA + 8 * WS + 4];
            const unsigned aB0 = sX[rA + 16 * WS];
            const unsigned aB1 = sX[rA + 24 * WS];
            const unsigned aB2 = sX[rA + 16 * WS + 4];
            const unsigned aB3 = sX[rA + 24 * WS + 4];
            unsigned bq[8];
            #pragma unroll
            for (int cf = 0; cf < 4; cf++) {
                bq[2 * cf]     = sW[(wc0 + cf * 8 + gid) * WS + k0 + tig];
                bq[2 * cf + 1] = sW[(wc0 + cf * 8 + gid) * WS + k0 + tig + 4];
            }
            #pragma unroll
            for (int cf = 0; cf < 4; cf++) {
                mma8(ccA[cf], aA0, aA1, aA2, aA3, bq[2 * cf], bq[2 * cf + 1]);
                mma8(ccB[cf], aB0, aB1, aB2, aB3, bq[2 * cf], bq[2 * cf + 1]);
            }
        }

        float* db = db_all + (size_t)c0 * HH;
        const int rr = wr0 + gid;
        #pragma unroll
        for (int cf = 0; cf < 4; cf++) {
            const int col = wc0 + cf * 8 + 2 * tig;
            *(float2*)&db[(rr     ) * HH + col] = make_float2(ccA[cf][0], ccA[cf][1]);
            *(float2*)&db[(rr +  8) * HH + col] = make_float2(ccA[cf][2], ccA[cf][3]);
            *(float2*)&db[(rr + 16) * HH + col] = make_float2(ccB[cf][0], ccB[cf][1]);
            *(float2*)&db[(rr + 24) * HH + col] = make_float2(ccB[cf][2], ccB[cf][3]);
        }
    }
}

// ---------------------------------------------------------------------------
// Kernel 2: flash attention per (b,n,j) — champion structure, raw-bit
// staging (unchanged from 196us build).
// smem = (512*20 + 512*24 + 512*20) * 4 = 131072 B
// ---------------------------------------------------------------------------
__global__ void __launch_bounds__(512) attn_kernel() {
    const int j = blockIdx.x;
    const int n = blockIdx.y;
    const int b = blockIdx.z;

    extern __shared__ unsigned smA[];
    unsigned* sK = smA;                         // [512][20]
    unsigned* sV = smA + 512 * 20;              // [512][24]
    unsigned* sQ = smA + 512 * 20 + 512 * 24;   // [512][20]; later P region

    const int tid  = threadIdx.x;
    const int warp = tid >> 5, lane = tid & 31;
    const int gid  = lane >> 2, tig = lane & 3;
    const size_t base = (size_t)((b * JJ + j) * SS) * HH + n * HSZ;

    // ---- stage Q, K, V as raw fp32 bits (pure 16B copies) ----
    {
        const int r = tid;
        const float* gq = &g_q[base + (size_t)r * HH];
        const float* gk = &g_k[base + (size_t)r * HH];
        const float* gv = &g_v[base + (size_t)r * HH];
        #pragma unroll
        for (int d4 = 0; d4 < 4; d4++) {
            *(float4*)&sQ[r * 20 + 4 * d4] = *(const float4*)(gq + 4 * d4);
            *(float4*)&sK[r * 20 + 4 * d4] = *(const float4*)(gk + 4 * d4);
            *(float4*)&sV[r * 24 + 4 * d4] = *(const float4*)(gv + 4 * d4);
        }
    }
    __syncthreads();

    unsigned qf[2][8];
    #pragma unroll
    for (int t = 0; t < 2; t++) {
        const int mt = t ? (31 - warp) : warp;
        const int r0 = mt * 16;
        #pragma unroll
        for (int kf = 0; kf < 2; kf++) {
            qf[t][kf * 4 + 0] = sQ[(r0 + gid) * 20 + kf * 8 + tig];
            qf[t][kf * 4 + 1] = sQ[(r0 + gid + 8) * 20 + kf * 8 + tig];
            qf[t][kf * 4 + 2] = sQ[(r0 + gid) * 20 + kf * 8 + tig + 4];
            qf[t][kf * 4 + 3] = sQ[(r0 + gid + 8) * 20 + kf * 8 + tig + 4];
        }
    }
    __syncthreads();  // sQ now reusable as P region

    unsigned* Pw = sQ + warp * 576;  // per-warp P: [16][36]

    #pragma unroll
    for (int t = 0; t < 2; t++) {
        const int mt = t ? (31 - warp) : warp;
        const int r0 = mt * 16;
        const int ktmax = (r0 + 15) >> 5;

        float m0 = -1e30f, m1 = -1e30f, l0 = 0.f, l1 = 0.f;
        float oc[2][4];
        #pragma unroll
        for (int on = 0; on < 2; on++)
            #pragma unroll
            for (int i = 0; i < 4; i++) oc[on][i] = 0.f;

        for (int kt = 0; kt <= ktmax; kt++) {
            const int k0 = kt * 32;

            float sc[4][4];
            #pragma unroll
            for (int nt = 0; nt < 4; nt++)
                #pragma unroll
                for (int i = 0; i < 4; i++) sc[nt][i] = 0.f;

            #pragma unroll
            for (int nt = 0; nt < 4; nt++) {
                #pragma unroll
                for (int kf = 0; kf < 2; kf++) {
                    const unsigned b0 = sK[(k0 + nt * 8 + gid) * 20 + kf * 8 + tig];
                    const unsigned b1 = sK[(k0 + nt * 8 + gid) * 20 + kf * 8 + tig + 4];
                    mma8(sc[nt], qf[t][kf * 4], qf[t][kf * 4 + 1],
                         qf[t][kf * 4 + 2], qf[t][kf * 4 + 3], b0, b1);
                }
            }

            if (kt == ktmax) {
                const int ra = r0 + gid, rb = ra + 8;
                #pragma unroll
                for (int nt = 0; nt < 4; nt++) {
                    const int key = k0 + nt * 8 + 2 * tig;
                    if (key     > ra) sc[nt][0] = -1e30f;
                    if (key + 1 > ra) sc[nt][1] = -1e30f;
                    if (key     > rb) sc[nt][2] = -1e30f;
                    if (key + 1 > rb) sc[nt][3] = -1e30f;
                }
            }

            float mx0 = fmaxf(fmaxf(sc[0][0], sc[0][1]), fmaxf(sc[1][0], sc[1][1]));
            mx0 = fmaxf(mx0, fmaxf(fmaxf(sc[2][0], sc[2][1]), fmaxf(sc[3][0], sc[3][1])));
            float mx1 = fmaxf(fmaxf(sc[0][2], sc[0][3]), fmaxf(sc[1][2], sc[1][3]));
            mx1 = fmaxf(mx1, fmaxf(fmaxf(sc[2][2], sc[2][3]), fmaxf(sc[3][2], sc[3][3])));
            mx0 = fmaxf(mx0, __shfl_xor_sync(0xFFFFFFFFu, mx0, 1));
            mx0 = fmaxf(mx0, __shfl_xor_sync(0xFFFFFFFFu, mx0, 2));
            mx1 = fmaxf(mx1, __shfl_xor_sync(0xFFFFFFFFu, mx1, 1));
            mx1 = fmaxf(mx1, __shfl_xor_sync(0xFFFFFFFFu, mx1, 2));

            const float mn0 = fmaxf(m0, mx0), mn1 = fmaxf(m1, mx1);
            const float c0 = __expf(m0 - mn0), c1 = __expf(m1 - mn1);
            m0 = mn0; m1 = mn1;
            l0 *= c0;  l1 *= c1;
            #pragma unroll
            for (int on = 0; on < 2; on++) {
                oc[on][0] *= c0; oc[on][1] *= c0;
                oc[on][2] *= c1; oc[on][3] *= c1;
            }

            #pragma unroll
            for (int nt = 0; nt < 4; nt++) {
                const float p0 = __expf(sc[nt][0] - m0);
                const float p1 = __expf(sc[nt][1] - m0);
                const float p2 = __expf(sc[nt][2] - m1);
                const float p3 = __expf(sc[nt][3] - m1);
                l0 += p0 + p1;  l1 += p2 + p3;
                *(float2*)&Pw[gid * 36 + nt * 8 + 2 * tig] = make_float2(p0, p1);
                *(float2*)&Pw[(gid + 8) * 36 + nt * 8 + 2 * tig] = make_float2(p2, p3);
            }
            __syncwarp();

            #pragma unroll
            for (int kf = 0; kf < 4; kf++) {
                const unsigned a0 = Pw[gid * 36 + kf * 8 + tig];
                const unsigned a1 = Pw[(gid + 8) * 36 + kf * 8 + tig];
                const unsigned a2 = Pw[gid * 36 + kf * 8 + tig + 4];
                const unsigned a3 = Pw[(gid + 8) * 36 + kf * 8 + tig + 4];
                #pragma unroll
                for (int on = 0; on < 2; on++) {
                    const unsigned b0 = sV[(k0 + kf * 8 + tig) * 24 + on * 8 + gid];
                    const unsigned b1 = sV[(k0 + kf * 8 + tig + 4) * 24 + on * 8 + gid];
                    mma8(oc[on], a0, a1, a2, a3, b0, b1);
                }
            }
            __syncwarp();
        }

        l0 += __shfl_xor_sync(0xFFFFFFFFu, l0, 1);
        l0 += __shfl_xor_sync(0xFFFFFFFFu, l0, 2);
        l1 += __shfl_xor_sync(0xFFFFFFFFu, l1, 1);
        l1 += __shfl_xor_sync(0xFFFFFFFFu, l1, 2);
        const float i0 = 1.f / l0, i1 = 1.f / l1;
        const int ra = r0 + gid, rb = ra + 8;
        #pragma unroll
        for (int on = 0; on < 2; on++) {
            const int col = n * HSZ + on * 8 + 2 * tig;
            *(float2*)&g_ao[((size_t)(b * SS + ra) * JJ + j) * HH + col] =
                make_float2(oc[on][0] * i0, oc[on][1] * i0);
            *(float2*)&g_ao[((size_t)(b * SS + rb) * JJ + j) * HH + col] =
                make_float2(oc[on][2] * i1, oc[on][3] * i1);
        }
    }
}

// ---------------------------------------------------------------------------
// Kernel 3: output projection + residual + LN. Row-split: 64 rows per block
// (single chunk). grid (24, 32), block 256, smem = 101376 B.
// Weights rounded (rna), activations raw bits.
// ---------------------------------------------------------------------------
__global__ void __launch_bounds__(256) proj_ln_kernel(const float* __restrict__ P,
                                                      const float* __restrict__ x,
                                                      const float* __restrict__ gamma,
                                                      const float* __restrict__ beta,
                                                      float* __restrict__ out) {
    const int j  = blockIdx.x;
    const int r0 = blockIdx.y * 64;

    extern __shared__ unsigned smu3[];
    unsigned* sPt = smu3;             // [k_out][h], stride WS
    unsigned* sA  = smu3 + HH * WS;   // [64 rows][h], stride WS; reused for C
    float* sC = (float*)sA;

    const int tid  = threadIdx.x;
    const int warp = tid >> 5, lane = tid & 31;
    const int gid  = lane >> 2, tig = lane & 3;
    const int wr0  = (warp & 1) * 32;
    const int wc0  = (warp >> 1) * 32;

    const float4 g4 = *(const float4*)(gamma + lane * 4);
    const float4 b4 = *(const float4*)(beta  + lane * 4);

    // prefetch A rows first (globals), then weights (L2-resident)
    float4 ar[8];
    #pragma unroll
    for (int q = 0; q < 8; q++) {
        const int i4 = tid + q * 256;
        const int r = i4 >> 5, h = (i4 & 31) * 4;
        ar[q] = *(const float4*)&g_ao[(size_t)((r0 + r) * JJ + j) * HH + h];
    }

    for (int i4 = tid; i4 < (HH * HH) / 4; i4 += 256) {
        const int idx = i4 * 4;
        const int h = idx >> 7, k = idx & 127;
        const float4 w = *(const float4*)&P[(size_t)j * HH * HH + idx];
        sPt[(k + 0) * WS + h] = f2tf32(w.x);
        sPt[(k + 1) * WS + h] = f2tf32(w.y);
        sPt[(k + 2) * WS + h] = f2tf32(w.z);
        sPt[(k + 3) * WS + h] = f2tf32(w.w);
    }

    #pragma unroll
    for (int q = 0; q < 8; q++) {
        const int i4 = tid + q * 256;
        const int r = i4 >> 5, h = (i4 & 31) * 4;
        *(float4*)&sA[r * WS + h] = ar[q];   // raw bits
    }
    __syncthreads();

    float ccA[4][4], ccB[4][4];
    #pragma unroll
    for (int cf = 0; cf < 4; cf++)
        #pragma unroll
        for (int i = 0; i < 4; i++) { ccA[cf][i] = 0.f; ccB[cf][i] = 0.f; }

    #pragma unroll
    for (int k0 = 0; k0 < HH; k0 += 8) {
        const int rA = (wr0 + gid) * WS + k0 + tig;
        const unsigned aA0 = sA[rA];
        const unsigned aA1 = sA[rA + 8 * WS];
        const unsigned aA2 = sA[rA + 4];
        const unsigned aA3 = sA[rA + 8 * WS + 4];
        const unsigned aB0 = sA[rA + 16 * WS];
        const unsigned aB1 = sA[rA + 24 * WS];
        const unsigned aB2 = sA[rA + 16 * WS + 4];
        const unsigned aB3 = sA[rA + 24 * WS + 4];
        unsigned bq[8];
        #pragma unroll
        for (int cf = 0; cf < 4; cf++) {
            bq[2 * cf]     = sPt[(wc0 + cf * 8 + gid) * WS + k0 + tig];
            bq[2 * cf + 1] = sPt[(wc0 + cf * 8 + gid) * WS + k0 + tig + 4];
        }
        #pragma unroll
        for (int cf = 0; cf < 4; cf++) {
            mma8(ccA[cf], aA0, aA1, aA2, aA3, bq[2 * cf], bq[2 * cf + 1]);
            mma8(ccB[cf], aB0, aB1, aB2, aB3, bq[2 * cf], bq[2 * cf + 1]);
        }
    }

    __syncthreads();  // all reads of sA done before overwrite as sC

    #pragma unroll
    for (int cf = 0; cf < 4; cf++) {
        const int col = wc0 + cf * 8 + 2 * tig;
        *(float2*)&sC[(wr0 + gid     ) * WS + col] = make_float2(ccA[cf][0], ccA[cf][1]);
        *(float2*)&sC[(wr0 + gid +  8) * WS + col] = make_float2(ccA[cf][2], ccA[cf][3]);
        *(float2*)&sC[(wr0 + gid + 16) * WS + col] = make_float2(ccB[cf][0], ccB[cf][1]);
        *(float2*)&sC[(wr0 + gid + 24) * WS + col] = make_float2(ccB[cf][2], ccB[cf][3]);
    }
    __syncthreads();

    // ---- fused residual + LayerNorm, warp-per-row (8 rows per warp) ----
    #pragma unroll
    for (int rr = 0; rr < 8; rr++) {
        const int r  = warp * 8 + rr;
        const int gr = r0 + r;
        const float4 c  = *(const float4*)&sC[r * WS + lane * 4];
        const float4 xr = *(const float4*)&x[((size_t)gr * JJ + j) * HH + lane * 4];
        const float v0 = c.x + xr.x, v1 = c.y + xr.y;
        const float v2 = c.z + xr.z, v3 = c.w + xr.w;

        float sum = v0 + v1 + v2 + v3;
        float sq  = v0 * v0 + v1 * v1 + v2 * v2 + v3 * v3;
        #pragma unroll
        for (int d = 16; d; d >>= 1) {
            sum += __shfl_xor_sync(0xFFFFFFFFu, sum, d);
            sq  += __shfl_xor_sync(0xFFFFFFFFu, sq, d);
        }
        const float mu  = sum * (1.f / 128.f);
        const float var = sq * (1.f / 128.f) - mu * mu;
        const float rs  = rsqrtf(var + 1e-5f);

        float4 o;
        o.x = (v0 - mu) * rs * g4.x + b4.x;
        o.y = (v1 - mu) * rs * g4.y + b4.y;
        o.z = (v2 - mu) * rs * g4.z + b4.z;
        o.w = (v3 - mu) * rs * g4.w + b4.w;
        *(float4*)&out[((size_t)gr * JJ + j) * HH + lane * 4] = o;
    }
}

// ---------------------------------------------------------------------------
extern "C" void kernel_launch(void* const* d_in, const int* in_sizes, int n_in,
                              void* d_out, int out_size) {
    const float* x     = (const float*)d_in[0];
    const float* qm    = (const float*)d_in[2];
    const float* km    = (const float*)d_in[3];
    const float* vm    = (const float*)d_in[4];
    const float* pmat  = (const float*)d_in[5];
    const float* gamma = (const float*)d_in[6];
    const float* beta  = (const float*)d_in[7];
    float* out = (float*)d_out;

    const int smem_mma  = (HH + 64) * WS * sizeof(unsigned);      // 101376
    const int smem_attn = (512 * 20 + 512 * 24 + 512 * 20) * 4;   // 131072

    cudaFuncSetAttribute(qkv_kernel,     cudaFuncAttributeMaxDynamicSharedMemorySize, smem_mma);
    cudaFuncSetAttribute(attn_kernel,    cudaFuncAttributeMaxDynamicSharedMemorySize, smem_attn);
    cudaFuncSetAttribute(proj_ln_kernel, cudaFuncAttributeMaxDynamicSharedMemorySize, smem_mma);

    dim3 g1(JJ, BB * 2, 3);
    qkv_kernel<<<g1, 256, smem_mma>>>(x, qm, km, vm);

    dim3 g2(JJ, NHEAD, BB);
    attn_kernel<<<g2, 512, smem_attn>>>();

    dim3 g3(JJ, (BB * SS) / 64);
    proj_ln_kernel<<<g3, 256, smem_mma>>>(pmat, x, gamma, beta, out);
}

// round 16
// speedup vs baseline: 1.1150x; 1.1150x over previous
#include <cuda_runtime.h>
#include <math.h>

#define BB 4
#define SS 512
#define JJ 24
#define HH 128
#define NHEAD 8
#define HSZ 16
#define WS 132   // padded smem stride for GEMM kernels

// Scratch (device globals — no allocation allowed)
// q/k/v layout: (b, j, s, col) with col = n*16 + d
// NOTE: g_q holds Q pre-scaled by log2(e)/sqrt(16) (folded into W_q at load),
// so attention scores are in the log2 domain and softmax uses exp2f.
__device__ float g_q[BB*JJ*SS*HH];
__device__ float g_k[BB*JJ*SS*HH];
__device__ float g_v[BB*JJ*SS*HH];
__device__ float g_ao[BB*SS*JJ*HH];   // attention out, (b,s,j,h) h=n*16+d

// ---- tf32 helpers ----------------------------------------------------------
__device__ __forceinline__ unsigned f2tf32(float f) {
    unsigned r; asm("cvt.rna.tf32.f32 %0, %1;" : "=r"(r) : "f"(f)); return r;
}
// tf32 mma: activation operands are raw fp32 bits (HW truncates); weights rounded.
__device__ __forceinline__ void mma8(float* c, unsigned a0, unsigned a1,
                                     unsigned a2, unsigned a3,
                                     unsigned b0, unsigned b1) {
    asm("mma.sync.aligned.m16n8k8.row.col.f32.tf32.tf32.f32 "
        "{%0,%1,%2,%3},{%4,%5,%6,%7},{%8,%9},{%0,%1,%2,%3};"
        : "+f"(c[0]), "+f"(c[1]), "+f"(c[2]), "+f"(c[3])
        : "r"(a0), "r"(a1), "r"(a2), "r"(a3), "r"(b0), "r"(b1));
}

// ---------------------------------------------------------------------------
// Kernel 1: QKV projection via tf32 mma (champion grid: (24,4,3), 512 rows).
// Weights rounded (rna) with scale folded into W_q; X raw bits.
// block 256, smem = (128+64)*132*4 = 101376 B
// ---------------------------------------------------------------------------
__global__ void __launch_bounds__(256) qkv_kernel(const float* __restrict__ x,
                           const float* __restrict__ qm,
                           const float* __restrict__ km,
                           const float* __restrict__ vm) {
    const int j = blockIdx.x;
    const int b = blockIdx.y;
    const int m = blockIdx.z;
    const float* W = (m == 0) ? qm : ((m == 1) ? km : vm);
    float* dst = (m == 0) ? g_q : ((m == 1) ? g_k : g_v);
    // fold (1/sqrt(HS)) * log2(e) into W_q: scores land in log2 domain
    const float wscale = (m == 0) ? 0.25f * 1.4426950408889634f : 1.0f;

    extern __shared__ unsigned smu[];
    unsigned* sW = smu;             // [col][h] transposed, stride WS
    unsigned* sX = smu + HH * WS;   // [64 rows][h], stride WS

    const int tid  = threadIdx.x;
    const int warp = tid >> 5, lane = tid & 31;
    const int gid  = lane >> 2, tig = lane & 3;
    const int wr0  = (warp & 1) * 32;
    const int wc0  = (warp >> 1) * 32;

    // one-time weight load: rounded tf32 (outside hot loop)
    for (int i4 = tid; i4 < (HH * HH) / 4; i4 += 256) {
        const int idx = i4 * 4;
        const int n8 = idx >> 11, rem = idx & 2047;
        const int h = rem >> 4, d = rem & 15;
        const float4 w = *(const float4*)&W[(size_t)(n8 * JJ + j) * 2048 + rem];
        const int col = n8 * HSZ + d;
        sW[(col + 0) * WS + h] = f2tf32(w.x * wscale);
        sW[(col + 1) * WS + h] = f2tf32(w.y * wscale);
        sW[(col + 2) * WS + h] = f2tf32(w.z * wscale);
        sW[(col + 3) * WS + h] = f2tf32(w.w * wscale);
    }

    float* db_all = dst + (size_t)((b * JJ + j) * SS) * HH;

    float4 xr[8];
    #pragma unroll
    for (int q = 0; q < 8; q++) {
        const int i4 = tid + q * 256;
        const int r = i4 >> 5, h = (i4 & 31) * 4;
        xr[q] = *(const float4*)&x[((size_t)(b * SS + r) * JJ + j) * HH + h];
    }

    for (int c0 = 0; c0 < SS; c0 += 64) {
        __syncthreads();
        #pragma unroll
        for (int q = 0; q < 8; q++) {
            const int i4 = tid + q * 256;
            const int r = i4 >> 5, h = (i4 & 31) * 4;
            *(float4*)&sX[r * WS + h] = xr[q];   // raw bits, no cvt
        }
        if (c0 + 64 < SS) {
            #pragma unroll
            for (int q = 0; q < 8; q++) {
                const int i4 = tid + q * 256;
                const int r = i4 >> 5, h = (i4 & 31) * 4;
                xr[q] = *(const float4*)&x[((size_t)(b * SS + c0 + 64 + r) * JJ + j) * HH + h];
            }
        }
        __syncthreads();

        float ccA[4][4], ccB[4][4];
        #pragma unroll
        for (int cf = 0; cf < 4; cf++)
            #pragma unroll
            for (int i = 0; i < 4; i++) { ccA[cf][i] = 0.f; ccB[cf][i] = 0.f; }

        #pragma unroll
        for (int k0 = 0; k0 < HH; k0 += 8) {
            const int rA = (wr0 + gid) * WS + k0 + tig;
            const unsigned aA0 = sX[rA];
            const unsigned aA1 = sX[rA + 8 * WS];
            const unsigned aA2 = sX[rA + 4];
            const unsigned aA3 = sX[rA + 8 * WS + 4];
            const unsigned aB0 = sX[rA + 16 * WS];
            const unsigned aB1 = sX[rA + 24 * WS];
            const unsigned aB2 = sX[rA + 16 * WS + 4];
            const unsigned aB3 = sX[rA + 24 * WS + 4];
            unsigned bq[8];
            #pragma unroll
            for (int cf = 0; cf < 4; cf++) {
                bq[2 * cf]     = sW[(wc0 + cf * 8 + gid) * WS + k0 + tig];
                bq[2 * cf + 1] = sW[(wc0 + cf * 8 + gid) * WS + k0 + tig + 4];
            }
            #pragma unroll
            for (int cf = 0; cf < 4; cf++) {
                mma8(ccA[cf], aA0, aA1, aA2, aA3, bq[2 * cf], bq[2 * cf + 1]);
                mma8(ccB[cf], aB0, aB1, aB2, aB3, bq[2 * cf], bq[2 * cf + 1]);
            }
        }

        float* db = db_all + (size_t)c0 * HH;
        const int rr = wr0 + gid;
        #pragma unroll
        for (int cf = 0; cf < 4; cf++) {
            const int col = wc0 + cf * 8 + 2 * tig;
            *(float2*)&db[(rr     ) * HH + col] = make_float2(ccA[cf][0], ccA[cf][1]);
            *(float2*)&db[(rr +  8) * HH + col] = make_float2(ccA[cf][2], ccA[cf][3]);
            *(float2*)&db[(rr + 16) * HH + col] = make_float2(ccB[cf][0], ccB[cf][1]);
            *(float2*)&db[(rr + 24) * HH + col] = make_float2(ccB[cf][2], ccB[cf][3]);
        }
    }
}

// ---------------------------------------------------------------------------
// Kernel 2: flash attention per (b,n,j) — champion structure, raw-bit
// staging; softmax in log2 domain (exp2f, scale folded into W_q).
// smem = (512*20 + 512*24 + 512*20) * 4 = 131072 B
// ---------------------------------------------------------------------------
__global__ void __launch_bounds__(512) attn_kernel() {
    const int j = blockIdx.x;
    const int n = blockIdx.y;
    const int b = blockIdx.z;

    extern __shared__ unsigned smA[];
    unsigned* sK = smA;                         // [512][20]
    unsigned* sV = smA + 512 * 20;              // [512][24]
    unsigned* sQ = smA + 512 * 20 + 512 * 24;   // [512][20]; later P region

    const int tid  = threadIdx.x;
    const int warp = tid >> 5, lane = tid & 31;
    const int gid  = lane >> 2, tig = lane & 3;
    const size_t base = (size_t)((b * JJ + j) * SS) * HH + n * HSZ;

    // ---- stage Q, K, V as raw fp32 bits (pure 16B copies) ----
    {
        const int r = tid;
        const float* gq = &g_q[base + (size_t)r * HH];
        const float* gk = &g_k[base + (size_t)r * HH];
        const float* gv = &g_v[base + (size_t)r * HH];
        #pragma unroll
        for (int d4 = 0; d4 < 4; d4++) {
            *(float4*)&sQ[r * 20 + 4 * d4] = *(const float4*)(gq + 4 * d4);
            *(float4*)&sK[r * 20 + 4 * d4] = *(const float4*)(gk + 4 * d4);
            *(float4*)&sV[r * 24 + 4 * d4] = *(const float4*)(gv + 4 * d4);
        }
    }
    __syncthreads();

    unsigned qf[2][8];
    #pragma unroll
    for (int t = 0; t < 2; t++) {
        const int mt = t ? (31 - warp) : warp;
        const int r0 = mt * 16;
        #pragma unroll
        for (int kf = 0; kf < 2; kf++) {
            qf[t][kf * 4 + 0] = sQ[(r0 + gid) * 20 + kf * 8 + tig];
            qf[t][kf * 4 + 1] = sQ[(r0 + gid + 8) * 20 + kf * 8 + tig];
            qf[t][kf * 4 + 2] = sQ[(r0 + gid) * 20 + kf * 8 + tig + 4];
            qf[t][kf * 4 + 3] = sQ[(r0 + gid + 8) * 20 + kf * 8 + tig + 4];
        }
    }
    __syncthreads();  // sQ now reusable as P region

    unsigned* Pw = sQ + warp * 576;  // per-warp P: [16][36]

    #pragma unroll
    for (int t = 0; t < 2; t++) {
        const int mt = t ? (31 - warp) : warp;
        const int r0 = mt * 16;
        const int ktmax = (r0 + 15) >> 5;

        float m0 = -1e30f, m1 = -1e30f, l0 = 0.f, l1 = 0.f;
        float oc[2][4];
        #pragma unroll
        for (int on = 0; on < 2; on++)
            #pragma unroll
            for (int i = 0; i < 4; i++) oc[on][i] = 0.f;

        for (int kt = 0; kt <= ktmax; kt++) {
            const int k0 = kt * 32;

            float sc[4][4];
            #pragma unroll
            for (int nt = 0; nt < 4; nt++)
                #pragma unroll
                for (int i = 0; i < 4; i++) sc[nt][i] = 0.f;

            #pragma unroll
            for (int nt = 0; nt < 4; nt++) {
                #pragma unroll
                for (int kf = 0; kf < 2; kf++) {
                    const unsigned b0 = sK[(k0 + nt * 8 + gid) * 20 + kf * 8 + tig];
                    const unsigned b1 = sK[(k0 + nt * 8 + gid) * 20 + kf * 8 + tig + 4];
                    mma8(sc[nt], qf[t][kf * 4], qf[t][kf * 4 + 1],
                         qf[t][kf * 4 + 2], qf[t][kf * 4 + 3], b0, b1);
                }
            }

            if (kt == ktmax) {
                const int ra = r0 + gid, rb = ra + 8;
                #pragma unroll
                for (int nt = 0; nt < 4; nt++) {
                    const int key = k0 + nt * 8 + 2 * tig;
                    if (key     > ra) sc[nt][0] = -1e30f;
                    if (key + 1 > ra) sc[nt][1] = -1e30f;
                    if (key     > rb) sc[nt][2] = -1e30f;
                    if (key + 1 > rb) sc[nt][3] = -1e30f;
                }
            }

            float mx0 = fmaxf(fmaxf(sc[0][0], sc[0][1]), fmaxf(sc[1][0], sc[1][1]));
            mx0 = fmaxf(mx0, fmaxf(fmaxf(sc[2][0], sc[2][1]), fmaxf(sc[3][0], sc[3][1])));
            float mx1 = fmaxf(fmaxf(sc[0][2], sc[0][3]), fmaxf(sc[1][2], sc[1][3]));
            mx1 = fmaxf(mx1, fmaxf(fmaxf(sc[2][2], sc[2][3]), fmaxf(sc[3][2], sc[3][3])));
            mx0 = fmaxf(mx0, __shfl_xor_sync(0xFFFFFFFFu, mx0, 1));
            mx0 = fmaxf(mx0, __shfl_xor_sync(0xFFFFFFFFu, mx0, 2));
            mx1 = fmaxf(mx1, __shfl_xor_sync(0xFFFFFFFFu, mx1, 1));
            mx1 = fmaxf(mx1, __shfl_xor_sync(0xFFFFFFFFu, mx1, 2));

            // log2-domain online softmax: single EX2 per value, no FMUL
            const float mn0 = fmaxf(m0, mx0), mn1 = fmaxf(m1, mx1);
            const float c0 = exp2f(m0 - mn0), c1 = exp2f(m1 - mn1);
            m0 = mn0; m1 = mn1;
            l0 *= c0;  l1 *= c1;
            #pragma unroll
            for (int on = 0; on < 2; on++) {
                oc[on][0] *= c0; oc[on][1] *= c0;
                oc[on][2] *= c1; oc[on][3] *= c1;
            }

            #pragma unroll
            for (int nt = 0; nt < 4; nt++) {
                const float p0 = exp2f(sc[nt][0] - m0);
                const float p1 = exp2f(sc[nt][1] - m0);
                const float p2 = exp2f(sc[nt][2] - m1);
                const float p3 = exp2f(sc[nt][3] - m1);
                l0 += p0 + p1;  l1 += p2 + p3;
                *(float2*)&Pw[gid * 36 + nt * 8 + 2 * tig] = make_float2(p0, p1);
                *(float2*)&Pw[(gid + 8) * 36 + nt * 8 + 2 * tig] = make_float2(p2, p3);
            }
            __syncwarp();

            #pragma unroll
            for (int kf = 0; kf < 4; kf++) {
                const unsigned a0 = Pw[gid * 36 + kf * 8 + tig];
                const unsigned a1 = Pw[(gid + 8) * 36 + kf * 8 + tig];
                const unsigned a2 = Pw[gid * 36 + kf * 8 + tig + 4];
                const unsigned a3 = Pw[(gid + 8) * 36 + kf * 8 + tig + 4];
                #pragma unroll
                for (int on = 0; on < 2; on++) {
                    const unsigned b0 = sV[(k0 + kf * 8 + tig) * 24 + on * 8 + gid];
                    const unsigned b1 = sV[(k0 + kf * 8 + tig + 4) * 24 + on * 8 + gid];
                    mma8(oc[on], a0, a1, a2, a3, b0, b1);
                }
            }
            __syncwarp();
        }

        l0 += __shfl_xor_sync(0xFFFFFFFFu, l0, 1);
        l0 += __shfl_xor_sync(0xFFFFFFFFu, l0, 2);
        l1 += __shfl_xor_sync(0xFFFFFFFFu, l1, 1);
        l1 += __shfl_xor_sync(0xFFFFFFFFu, l1, 2);
        const float i0 = 1.f / l0, i1 = 1.f / l1;
        const int ra = r0 + gid, rb = ra + 8;
        #pragma unroll
        for (int on = 0; on < 2; on++) {
            const int col = n * HSZ + on * 8 + 2 * tig;
            *(float2*)&g_ao[((size_t)(b * SS + ra) * JJ + j) * HH + col] =
                make_float2(oc[on][0] * i0, oc[on][1] * i0);
            *(float2*)&g_ao[((size_t)(b * SS + rb) * JJ + j) * HH + col] =
                make_float2(oc[on][2] * i1, oc[on][3] * i1);
        }
    }
}

// ---------------------------------------------------------------------------
// Kernel 3: output projection + residual + LN (champion grid (24,16)).
// Weights rounded (rna), activations raw bits.
// ---------------------------------------------------------------------------
__global__ void __launch_bounds__(256) proj_ln_kernel(const float* __restrict__ P,
                                                      const float* __restrict__ x,
                                                      const float* __restrict__ gamma,
                                                      const float* __restrict__ beta,
                                                      float* __restrict__ out) {
    const int j  = blockIdx.x;
    const int r0 = blockIdx.y * 128;

    extern __shared__ unsigned smu3[];
    unsigned* sPt = smu3;
    unsigned* sA  = smu3 + HH * WS;
    float* sC = (float*)sA;

    const int tid  = threadIdx.x;
    const int warp = tid >> 5, lane = tid & 31;
    const int gid  = lane >> 2, tig = lane & 3;
    const int wr0  = (warp & 1) * 32;
    const int wc0  = (warp >> 1) * 32;

    const float4 g4 = *(const float4*)(gamma + lane * 4);
    const float4 b4 = *(const float4*)(beta  + lane * 4);

    for (int i4 = tid; i4 < (HH * HH) / 4; i4 += 256) {
        const int idx = i4 * 4;
        const int h = idx >> 7, k = idx & 127;
        const float4 w = *(const float4*)&P[(size_t)j * HH * HH + idx];
        sPt[(k + 0) * WS + h] = f2tf32(w.x);
        sPt[(k + 1) * WS + h] = f2tf32(w.y);
        sPt[(k + 2) * WS + h] = f2tf32(w.z);
        sPt[(k + 3) * WS + h] = f2tf32(w.w);
    }

    float4 ar[8];
    #pragma unroll
    for (int q = 0; q < 8; q++) {
        const int i4 = tid + q * 256;
        const int r = i4 >> 5, h = (i4 & 31) * 4;
        ar[q] = *(const float4*)&g_ao[(size_t)((r0 + r) * JJ + j) * HH + h];
    }

    for (int c0 = 0; c0 < 128; c0 += 64) {
        __syncthreads();
        #pragma unroll
        for (int q = 0; q < 8; q++) {
            const int i4 = tid + q * 256;
            const int r = i4 >> 5, h = (i4 & 31) * 4;
            *(float4*)&sA[r * WS + h] = ar[q];   // raw bits
        }
        if (c0 == 0) {
            #pragma unroll
            for (int q = 0; q < 8; q++) {
                const int i4 = tid + q * 256;
                const int r = i4 >> 5, h = (i4 & 31) * 4;
                ar[q] = *(const float4*)&g_ao[(size_t)((r0 + 64 + r) * JJ + j) * HH + h];
            }
        }
        __syncthreads();

        float ccA[4][4], ccB[4][4];
        #pragma unroll
        for (int cf = 0; cf < 4; cf++)
            #pragma unroll
            for (int i = 0; i < 4; i++) { ccA[cf][i] = 0.f; ccB[cf][i] = 0.f; }

        #pragma unroll
        for (int k0 = 0; k0 < HH; k0 += 8) {
            const int rA = (wr0 + gid) * WS + k0 + tig;
            const unsigned aA0 = sA[rA];
            const unsigned aA1 = sA[rA + 8 * WS];
            const unsigned aA2 = sA[rA + 4];
            const unsigned aA3 = sA[rA + 8 * WS + 4];
            const unsigned aB0 = sA[rA + 16 * WS];
            const unsigned aB1 = sA[rA + 24 * WS];
            const unsigned aB2 = sA[rA + 16 * WS + 4];
            const unsigned aB3 = sA[rA + 24 * WS + 4];
            unsigned bq[8];
            #pragma unroll
            for (int cf = 0; cf < 4; cf++) {
                bq[2 * cf]     = sPt[(wc0 + cf * 8 + gid) * WS + k0 + tig];
                bq[2 * cf + 1] = sPt[(wc0 + cf * 8 + gid) * WS + k0 + tig + 4];
            }
            #pragma unroll
            for (int cf = 0; cf < 4; cf++) {
                mma8(ccA[cf], aA0, aA1, aA2, aA3, bq[2 * cf], bq[2 * cf + 1]);
                mma8(ccB[cf], aB0, aB1, aB2, aB3, bq[2 * cf], bq[2 * cf + 1]);
            }
        }

        __syncthreads();

        #pragma unroll
        for (int cf = 0; cf < 4; cf++) {
            const int col = wc0 + cf * 8 + 2 * tig;
            *(float2*)&sC[(wr0 + gid     ) * WS + col] = make_float2(ccA[cf][0], ccA[cf][1]);
            *(float2*)&sC[(wr0 + gid +  8) * WS + col] = make_float2(ccA[cf][2], ccA[cf][3]);
            *(float2*)&sC[(wr0 + gid + 16) * WS + col] = make_float2(ccB[cf][0], ccB[cf][1]);
            *(float2*)&sC[(wr0 + gid + 24) * WS + col] = make_float2(ccB[cf][2], ccB[cf][3]);
        }
        __syncthreads();

        #pragma unroll
        for (int rr = 0; rr < 8; rr++) {
            const int r  = warp * 8 + rr;
            const int gr = r0 + c0 + r;
            const float4 c  = *(const float4*)&sC[r * WS + lane * 4];
            const float4 xr = *(const float4*)&x[((size_t)gr * JJ + j) * HH + lane * 4];
            const float v0 = c.x + xr.x, v1 = c.y + xr.y;
            const float v2 = c.z + xr.z, v3 = c.w + xr.w;

            float sum = v0 + v1 + v2 + v3;
            float sq  = v0 * v0 + v1 * v1 + v2 * v2 + v3 * v3;
            #pragma unroll
            for (int d = 16; d; d >>= 1) {
                sum += __shfl_xor_sync(0xFFFFFFFFu, sum, d);
                sq  += __shfl_xor_sync(0xFFFFFFFFu, sq, d);
            }
            const float mu  = sum * (1.f / 128.f);
            const float var = sq * (1.f / 128.f) - mu * mu;
            const float rs  = rsqrtf(var + 1e-5f);

            float4 o;
            o.x = (v0 - mu) * rs * g4.x + b4.x;
            o.y = (v1 - mu) * rs * g4.y + b4.y;
            o.z = (v2 - mu) * rs * g4.z + b4.z;
            o.w = (v3 - mu) * rs * g4.w + b4.w;
            *(float4*)&out[((size_t)gr * JJ + j) * HH + lane * 4] = o;
        }
    }
}

// ---------------------------------------------------------------------------
extern "C" void kernel_launch(void* const* d_in, const int* in_sizes, int n_in,
                              void* d_out, int out_size) {
    const float* x     = (const float*)d_in[0];
    const float* qm    = (const float*)d_in[2];
    const float* km    = (const float*)d_in[3];
    const float* vm    = (const float*)d_in[4];
    const float* pmat  = (const float*)d_in[5];
    const float* gamma = (const float*)d_in[6];
    const float* beta  = (const float*)d_in[7];
    float* out = (float*)d_out;

    const int smem_mma  = (HH + 64) * WS * sizeof(unsigned);      // 101376
    const int smem_attn = (512 * 20 + 512 * 24 + 512 * 20) * 4;   // 131072

    cudaFuncSetAttribute(qkv_kernel,     cudaFuncAttributeMaxDynamicSharedMemorySize, smem_mma);
    cudaFuncSetAttribute(attn_kernel,    cudaFuncAttributeMaxDynamicSharedMemorySize, smem_attn);
    cudaFuncSetAttribute(proj_ln_kernel, cudaFuncAttributeMaxDynamicSharedMemorySize, smem_mma);

    dim3 g1(JJ, BB, 3);
    qkv_kernel<<<g1, 256, smem_mma>>>(x, qm, km, vm);

    dim3 g2(JJ, NHEAD, BB);
    attn_kernel<<<g2, 512, smem_attn>>>();

    dim3 g3(JJ, (BB * SS) / 128);
    proj_ln_kernel<<<g3, 256, smem_mma>>>(pmat, x, gamma, beta, out);
}